// round 3
// baseline (speedup 1.0000x reference)
#include <cuda_runtime.h>
#include <cstdint>
#include <cstddef>

#define NN 100000
#define NE 1600000
#define FD 128
#define NC 10
#define CP 16          // padded row stride (64B-aligned rows; 10 floats used)
#define NG 64

// ---------------- device scratch (allocation-free rule) ----------------
__device__ __align__(128) float g_y0[(size_t)NN * CP];   // X @ W12
__device__ __align__(128) float g_y1[(size_t)NN * CP];   // S @ y0
__device__ __align__(128) float g_y2[(size_t)NN * CP];   // S @ y1
__device__ float g_dis[NN];               // deg^{-1/2}
__device__ int   g_deg[NN];
__device__ float g_uacc[NN];              // sum_{r->i} dis[r]
__device__ float g_u[NN];                 // (S·1)[i]
__device__ float g_vacc[NN];              // sum_{r->i} dis[r]*u[r]
__device__ float g_W12[FD * CP];          // W1@W2, padded
__device__ float g_c1[NC];                // W2^T b1
__device__ float g_pool[NG * NC];
__device__ float g_pu[NG];
__device__ float g_pv[NG];
__device__ int   g_cnt[NG];
__device__ int   g_is64;

// ---------------- helpers ----------------
__device__ __forceinline__ int ld_idx(const void* p, long long i, int is64) {
    if (is64) return (int)((const long long*)p)[i];
    return ((const int*)p)[i];
}

__device__ __forceinline__ void red_add_v4(float* p, float4 v) {
    asm volatile("red.global.add.v4.f32 [%0], {%1,%2,%3,%4};"
                 :: "l"(p), "f"(v.x), "f"(v.y), "f"(v.z), "f"(v.w)
                 : "memory");
}
__device__ __forceinline__ void red_add_v2(float* p, float2 v) {
    asm volatile("red.global.add.v2.f32 [%0], {%1,%2};"
                 :: "l"(p), "f"(v.x), "f"(v.y)
                 : "memory");
}

// ---------------- kernels ----------------

// init accumulators; block 0 also runs int64-vs-int32 probe on edge_index:
// node ids < 2^31, so int64 <=> high words of first 4096 8B-words all zero.
__global__ void k_init(const unsigned* __restrict__ w) {
    int i = blockIdx.x * 256 + threadIdx.x;
    if (i < NN) { g_deg[i] = 1; g_uacc[i] = 0.f; g_vacc[i] = 0.f; }
    if (i < NG * NC) g_pool[i] = 0.f;
    if (i < NG) { g_pu[i] = 0.f; g_pv[i] = 0.f; g_cnt[i] = 0; }
    if (blockIdx.x == 0) {
        __shared__ unsigned s;
        if (threadIdx.x == 0) s = 0u;
        __syncthreads();
        unsigned a = 0;
        for (int j = threadIdx.x; j < 4096; j += 256) a |= w[2 * j + 1];
        atomicOr(&s, a);
        __syncthreads();
        if (threadIdx.x == 0) g_is64 = (s == 0u) ? 1 : 0;
    }
}

// W12 = W1 @ W2 (padded stride CP), c1 = W2^T b1
__global__ void k_w12(const float* __restrict__ W1,
                      const float* __restrict__ W2,
                      const float* __restrict__ b1) {
    int tid = blockIdx.x * 256 + threadIdx.x;
    for (int idx = tid; idx < FD * CP; idx += gridDim.x * 256) {
        int k = idx / CP, c = idx - k * CP;
        float s = 0.f;
        if (c < NC) {
            for (int j = 0; j < FD; j++)
                s += W1[k * FD + j] * __ldg(W2 + j * NC + c);
        }
        g_W12[idx] = s;
    }
    if (blockIdx.x == 0 && threadIdx.x < NC) {
        int c = threadIdx.x;
        float s = 0.f;
        for (int j = 0; j < FD; j++) s += b1[j] * __ldg(W2 + j * NC + c);
        g_c1[c] = s;
    }
}

__global__ void k_deg(const void* __restrict__ ei) {
    int e = blockIdx.x * 256 + threadIdx.x;
    if (e >= NE) return;
    int c = ld_idx(ei, (long long)NE + e, g_is64);
    atomicAdd(&g_deg[c], 1);
}

__global__ void k_dis() {
    int i = blockIdx.x * 256 + threadIdx.x;
    if (i < NN) g_dis[i] = rsqrtf((float)g_deg[i]);
}

// Y0 = X @ W12 and Y1 = dis^2 * Y0 (self-loop term), fused.
// Warp-per-node: lane holds W12 rows [4*lane, 4*lane+4) in registers, loads
// one float4 of X (coalesced 512B/warp), 40 FMA, butterfly-reduce 10 sums.
// After the butterfly every lane has all 10 totals -> distribute the stores.
__global__ void __launch_bounds__(256) k_gemm0(const float* __restrict__ x) {
    int lane = threadIdx.x & 31;
    int warpId = (blockIdx.x * 256 + threadIdx.x) >> 5;
    int nWarps = (gridDim.x * 256) >> 5;

    float w[4][NC];
#pragma unroll
    for (int kk = 0; kk < 4; kk++)
#pragma unroll
        for (int c = 0; c < NC; c++)
            w[kk][c] = g_W12[(lane * 4 + kk) * CP + c];

    for (int n = warpId; n < NN; n += nWarps) {
        float4 xv = *(const float4*)(x + (size_t)n * FD + lane * 4);
        float acc[NC];
#pragma unroll
        for (int c = 0; c < NC; c++) acc[c] = 0.f;
#pragma unroll
        for (int kk = 0; kk < 4; kk++) {
            float xk = ((const float*)&xv)[kk];
#pragma unroll
            for (int c = 0; c < NC; c++) acc[c] += xk * w[kk][c];
        }
#pragma unroll
        for (int o = 16; o > 0; o >>= 1)
#pragma unroll
            for (int c = 0; c < NC; c++)
                acc[c] += __shfl_xor_sync(0xffffffffu, acc[c], o);

        float d = g_dis[n];
        float s = d * d;
        float* d0 = g_y0 + (size_t)n * CP;
        float* d1 = g_y1 + (size_t)n * CP;
        if (lane == 0)      *(float4*)d0       = make_float4(acc[0], acc[1], acc[2], acc[3]);
        else if (lane == 1) *(float4*)(d0 + 4) = make_float4(acc[4], acc[5], acc[6], acc[7]);
        else if (lane == 2) *(float2*)(d0 + 8) = make_float2(acc[8], acc[9]);
        else if (lane == 4) *(float4*)d1       = make_float4(acc[0] * s, acc[1] * s, acc[2] * s, acc[3] * s);
        else if (lane == 5) *(float4*)(d1 + 4) = make_float4(acc[4] * s, acc[5] * s, acc[6] * s, acc[7] * s);
        else if (lane == 6) *(float2*)(d1 + 8) = make_float2(acc[8] * s, acc[9] * s);
    }
}

// edge pass A: y1[c] += dis[r]dis[c]*y0[r]   and   uacc[c] += dis[r]
__global__ void __launch_bounds__(256) k_passA(const void* __restrict__ ei) {
    int e = blockIdx.x * 256 + threadIdx.x;
    if (e >= NE) return;
    int is64 = g_is64;
    int r = ld_idx(ei, e, is64);
    int c = ld_idx(ei, (long long)NE + e, is64);
    float dr = g_dis[r], dc = g_dis[c];
    atomicAdd(&g_uacc[c], dr);
    float wgt = dr * dc;
    const float* src = g_y0 + (size_t)r * CP;
    float4 a = *(const float4*)src;
    float4 b = *(const float4*)(src + 4);
    float2 d = *(const float2*)(src + 8);
    a.x *= wgt; a.y *= wgt; a.z *= wgt; a.w *= wgt;
    b.x *= wgt; b.y *= wgt; b.z *= wgt; b.w *= wgt;
    d.x *= wgt; d.y *= wgt;
    float* dst = g_y1 + (size_t)c * CP;
    red_add_v4(dst, a);
    red_add_v4(dst + 4, b);
    red_add_v2(dst + 8, d);
}

// finalize u = (S·1), init y2 = dis^2 * y1 (self-loop term of layer 2)
__global__ void k_mid() {
    int n = blockIdx.x * 256 + threadIdx.x;
    if (n >= NN) return;
    float d = g_dis[n], s = d * d;
    g_u[n] = d * g_uacc[n] + s;          // u = dis*(uacc + dis)
    const float* sp = g_y1 + (size_t)n * CP;
    float* dp = g_y2 + (size_t)n * CP;
    float4 a = *(const float4*)sp;
    float4 b = *(const float4*)(sp + 4);
    float2 c = *(const float2*)(sp + 8);
    *(float4*)dp       = make_float4(a.x * s, a.y * s, a.z * s, a.w * s);
    *(float4*)(dp + 4) = make_float4(b.x * s, b.y * s, b.z * s, b.w * s);
    *(float2*)(dp + 8) = make_float2(c.x * s, c.y * s);
}

// edge pass B: y2[c] += dis[r]dis[c]*y1[r]   and   vacc[c] += dis[r]*u[r]
__global__ void __launch_bounds__(256) k_passB(const void* __restrict__ ei) {
    int e = blockIdx.x * 256 + threadIdx.x;
    if (e >= NE) return;
    int is64 = g_is64;
    int r = ld_idx(ei, e, is64);
    int c = ld_idx(ei, (long long)NE + e, is64);
    float dr = g_dis[r], dc = g_dis[c];
    atomicAdd(&g_vacc[c], dr * g_u[r]);
    float wgt = dr * dc;
    const float* src = g_y1 + (size_t)r * CP;
    float4 a = *(const float4*)src;
    float4 b = *(const float4*)(src + 4);
    float2 d = *(const float2*)(src + 8);
    a.x *= wgt; a.y *= wgt; a.z *= wgt; a.w *= wgt;
    b.x *= wgt; b.y *= wgt; b.z *= wgt; b.w *= wgt;
    d.x *= wgt; d.y *= wgt;
    float* dst = g_y2 + (size_t)c * CP;
    red_add_v4(dst, a);
    red_add_v4(dst + 4, b);
    red_add_v2(dst + 8, d);
}

// pooling: per-block shared combine (batch sorted => ~1-2 graphs/block)
__global__ void k_pool(const void* __restrict__ batch) {
    __shared__ float sp[NG * NC];
    __shared__ float su[NG], sv[NG];
    __shared__ int sc[NG];
    int tid = threadIdx.x;
    for (int i = tid; i < NG * NC; i += 256) sp[i] = 0.f;
    if (tid < NG) { su[tid] = 0.f; sv[tid] = 0.f; sc[tid] = 0; }
    __syncthreads();
    int n = blockIdx.x * 256 + tid;
    if (n < NN) {
        int g = ld_idx(batch, n, g_is64);
        float d = g_dis[n];
        float u = g_u[n];
        float v = d * (g_vacc[n] + d * u);   // v = (SS·1)[n]
        atomicAdd(&sc[g], 1);
        atomicAdd(&su[g], u);
        atomicAdd(&sv[g], v);
        const float* y = g_y2 + (size_t)n * CP;
#pragma unroll
        for (int c = 0; c < NC; c++) atomicAdd(&sp[g * NC + c], y[c]);
    }
    __syncthreads();
    for (int i = tid; i < NG * NC; i += 256)
        if (sp[i] != 0.f) atomicAdd(&g_pool[i], sp[i]);
    if (tid < NG) {
        if (sc[tid]) atomicAdd(&g_cnt[tid], sc[tid]);
        if (su[tid] != 0.f) atomicAdd(&g_pu[tid], su[tid]);
        if (sv[tid] != 0.f) atomicAdd(&g_pv[tid], sv[tid]);
    }
}

// combine rank-1 bias terms, mean, log_softmax, write [64,10]
__global__ void k_fin(const float* __restrict__ b2, float* __restrict__ out) {
    int g = threadIdx.x;
    if (g >= NG) return;
    float inv = 1.f / fmaxf((float)g_cnt[g], 1.f);
    float pu = g_pu[g], pv = g_pv[g];
    float v[NC];
    float m = -1e30f;
#pragma unroll
    for (int c = 0; c < NC; c++) {
        v[c] = (g_pool[g * NC + c] + pv * g_c1[c] + pu * __ldg(b2 + c)) * inv;
        m = fmaxf(m, v[c]);
    }
    float s = 0.f;
#pragma unroll
    for (int c = 0; c < NC; c++) s += expf(v[c] - m);
    float l = logf(s);
#pragma unroll
    for (int c = 0; c < NC; c++) out[g * NC + c] = v[c] - m - l;
}

// ---------------- launch ----------------
extern "C" void kernel_launch(void* const* d_in, const int* in_sizes, int n_in,
                              void* d_out, int out_size) {
    const float* x = nullptr;
    const void* ei = nullptr;
    const void* batch = nullptr;
    const float *W1 = nullptr, *b1 = nullptr, *W2 = nullptr, *b2 = nullptr;

    for (int i = 0; i < n_in; i++) {
        switch (in_sizes[i]) {
            case 12800000: x = (const float*)d_in[i]; break;      // x [100000,128]
            case 3200000:  ei = d_in[i]; break;                   // edge_index [2,1600000]
            case 100000:   batch = d_in[i]; break;                // batch
            case 16384:    W1 = (const float*)d_in[i]; break;     // W1 [128,128]
            case 128:      b1 = (const float*)d_in[i]; break;     // b1
            case 1280:     W2 = (const float*)d_in[i]; break;     // W2 [128,10]
            case 10:       b2 = (const float*)d_in[i]; break;     // b2
            default: break;                                       // num_graphs: unused
        }
    }
    float* out = (float*)d_out;

    const int NB_N = (NN + 255) / 256;
    const int NB_E = (NE + 255) / 256;

    k_init<<<NB_N, 256>>>((const unsigned*)ei);
    k_w12<<<8, 256>>>(W1, W2, b1);
    k_deg<<<NB_E, 256>>>(ei);
    k_dis<<<NB_N, 256>>>();
    k_gemm0<<<1184, 256>>>(x);
    k_passA<<<NB_E, 256>>>(ei);
    k_mid<<<NB_N, 256>>>();
    k_passB<<<NB_E, 256>>>(ei);
    k_pool<<<NB_N, 256>>>(batch);
    k_fin<<<1, 64>>>(b2, out);
}